// round 8
// baseline (speedup 1.0000x reference)
#include <cuda_runtime.h>
#include <math.h>

#define NT   8192        // tiles: bs(8) * n(32) * n(32)
#define NSM  148         // sm_100a
#define GRID (2 * NSM)   // 2 CTAs/SM persistent

static __device__ float g_P[64 * 256];     // P[pair][c], pair = m1*8+m2
static __device__ float g_A[NT * 256];     // A[t][c] = E_row(t) . W[c]

// ---------------------------------------------------------------------------
// Kernel 1 (prep): blocks 0..511 compute A, blocks 512..575 compute P.
// ---------------------------------------------------------------------------
#define AR 16
__global__ void __launch_bounds__(256) prep_kernel(
    const float* __restrict__ E, const float* __restrict__ W)
{
    __shared__ float sh[64 * 20];          // A: Est[d][r] stride 20; P: pe row
    const int tid = threadIdx.x;

    // W row for this thread's c: 16 independent vector loads (both roles)
    float4 w4[16];
    const float4* wp = (const float4*)(W + tid * 64);
#pragma unroll
    for (int i = 0; i < 16; ++i) w4[i] = wp[i];

    if (blockIdx.x < 512) {
        const int r0 = blockIdx.x * AR;
        for (int i = tid; i < AR * 64; i += 256) {
            int r = i >> 6, d = i & 63;
            sh[d * 20 + r] = E[(r0 + r) * 64 + d];
        }
        __syncthreads();

        float acc[AR];
#pragma unroll
        for (int r = 0; r < AR; ++r) acc[r] = 0.f;

#pragma unroll
        for (int d4 = 0; d4 < 16; ++d4) {
            float wv4[4] = {w4[d4].x, w4[d4].y, w4[d4].z, w4[d4].w};
#pragma unroll
            for (int s = 0; s < 4; ++s) {
                int d = d4 * 4 + s;
                float wv = wv4[s];
                const float4* ep = (const float4*)(sh + d * 20);
                float4 e0 = ep[0], e1 = ep[1], e2 = ep[2], e3 = ep[3];
                acc[0]  = fmaf(e0.x, wv, acc[0]);
                acc[1]  = fmaf(e0.y, wv, acc[1]);
                acc[2]  = fmaf(e0.z, wv, acc[2]);
                acc[3]  = fmaf(e0.w, wv, acc[3]);
                acc[4]  = fmaf(e1.x, wv, acc[4]);
                acc[5]  = fmaf(e1.y, wv, acc[5]);
                acc[6]  = fmaf(e1.z, wv, acc[6]);
                acc[7]  = fmaf(e1.w, wv, acc[7]);
                acc[8]  = fmaf(e2.x, wv, acc[8]);
                acc[9]  = fmaf(e2.y, wv, acc[9]);
                acc[10] = fmaf(e2.z, wv, acc[10]);
                acc[11] = fmaf(e2.w, wv, acc[11]);
                acc[12] = fmaf(e3.x, wv, acc[12]);
                acc[13] = fmaf(e3.y, wv, acc[13]);
                acc[14] = fmaf(e3.z, wv, acc[14]);
                acc[15] = fmaf(e3.w, wv, acc[15]);
            }
        }
#pragma unroll
        for (int r = 0; r < AR; ++r) g_A[(r0 + r) * 256 + tid] = acc[r];
    } else {
        const int p = blockIdx.x - 512;
        if (tid < 32) {
            float div = expf(-(float)tid * 0.28782313662425572f); // ln(1e4)/32
            float ang = (float)p * div;
            sh[2 * tid]     = sinf(ang);
            sh[2 * tid + 1] = cosf(ang);
        }
        __syncthreads();

        float a0 = 0.f, a1 = 0.f, a2 = 0.f, a3 = 0.f;
#pragma unroll
        for (int i = 0; i < 16; ++i) {
            a0 = fmaf(sh[4 * i + 0], w4[i].x, a0);
            a1 = fmaf(sh[4 * i + 1], w4[i].y, a1);
            a2 = fmaf(sh[4 * i + 2], w4[i].z, a2);
            a3 = fmaf(sh[4 * i + 3], w4[i].w, a3);
        }
        g_P[p * 256 + tid] = (a0 + a1) + (a2 + a3);
    }
}

// ---------------------------------------------------------------------------
// Kernel 2: persistent pure-store kernel. 512 threads/CTA, 2 CTAs/SM
// (32 warps/SM, occ 50%). Each thread owns ONE m2 value (grp = tid>>6) and
// 4 c-values (cq = tid&63): 8 streaming float4 stores per tile, Pr[8] = 32
// registers. No SMEM, no barriers; next tile's A row + masks prefetched
// before the store burst.
// ---------------------------------------------------------------------------
__global__ void __launch_bounds__(512, 2) etoc_store_kernel(
    const float* __restrict__ m1g,
    const float* __restrict__ m2g,
    float4* __restrict__ out4)
{
    const int tid = threadIdx.x;
    const int cq  = tid & 63;   // float4 column index within 256-wide c
    const int grp = tid >> 6;   // m2 index 0..7

    float4 Pr[8];
#pragma unroll
    for (int m1 = 0; m1 < 8; ++m1)
        Pr[m1] = *(const float4*)(g_P + (m1 * 8 + grp) * 256 + 4 * cq);

    int t = blockIdx.x;
    if (t >= NT) return;

    // Prologue loads for first tile
    int b  = t >> 10, i1 = (t >> 5) & 31, j1 = t & 31;
    float4 a4  = *(const float4*)(g_A + t * 256 + 4 * cq);
    float  m1v = __ldg(m1g + b * 32 + i1);
    float  m2v = __ldg(m2g + b * 32 + ((j1 * 8 + grp) & 31));

    while (true) {
        // Prefetch next tile
        int tn = t + GRID;
        float4 a4n;
        float  m1n = 0.f, m2n = 0.f;
        bool   more = tn < NT;
        if (more) {
            int bn = tn >> 10, i1n = (tn >> 5) & 31, j1n = tn & 31;
            a4n = *(const float4*)(g_A + tn * 256 + 4 * cq);
            m1n = __ldg(m1g + bn * 32 + i1n);
            m2n = __ldg(m2g + bn * 32 + ((j1n * 8 + grp) & 31));
        }

        // Compute + store current tile (64 KB per CTA)
        float f = m1v * m2v;
        float4 fa = {f * a4.x, f * a4.y, f * a4.z, f * a4.w};

        float4* p0 = out4 +
            ((unsigned)(b * 256 + i1 * 8) * 256u + (unsigned)(j1 * 8 + grp)) * 64u
            + (unsigned)cq;

#pragma unroll
        for (int m1 = 0; m1 < 8; ++m1) {
            float4 p = Pr[m1];
            float4 v;
            v.x = fmaf(f, p.x, fa.x);
            v.y = fmaf(f, p.y, fa.y);
            v.z = fmaf(f, p.z, fa.z);
            v.w = fmaf(f, p.w, fa.w);
            __stcs(p0 + m1 * 16384, v);
        }

        if (!more) break;
        t = tn;
        b = t >> 10; i1 = (t >> 5) & 31; j1 = t & 31;
        a4 = a4n; m1v = m1n; m2v = m2n;
    }
}

// ---------------------------------------------------------------------------
// Launch
// ---------------------------------------------------------------------------
extern "C" void kernel_launch(void* const* d_in, const int* in_sizes, int n_in,
                              void* d_out, int out_size) {
    const float* E  = (const float*)d_in[0];  // (8,32,32,64)
    const float* m1 = (const float*)d_in[1];  // (8,32,1,1)
    const float* m2 = (const float*)d_in[2];  // (8,1,32,1)
    const float* W  = (const float*)d_in[3];  // (256,64)

    prep_kernel<<<512 + 64, 256>>>(E, W);
    etoc_store_kernel<<<GRID, 512>>>(m1, m2, (float4*)d_out);
}

// round 9
// speedup vs baseline: 1.0152x; 1.0152x over previous
#include <cuda_runtime.h>
#include <math.h>
#include <stdint.h>

#define NT   8192        // tiles: bs(8) * n(32) * n(32)
#define NSM  148         // sm_100a
#define GRID NSM         // 1 CTA/SM persistent (double-buffered 128KB SMEM)

static __device__ float g_P[64 * 256];     // P[pair][c], pair = m1*8+m2
static __device__ float g_A[NT * 256];     // A[t][c] = E_row(t) . W[c]

// ---------------------------------------------------------------------------
// Kernel 1 (prep): blocks 0..511 compute A, blocks 512..575 compute P.
// ---------------------------------------------------------------------------
#define AR 16
__global__ void __launch_bounds__(256) prep_kernel(
    const float* __restrict__ E, const float* __restrict__ W)
{
    __shared__ float sh[64 * 20];          // A: Est[d][r] stride 20; P: pe row
    const int tid = threadIdx.x;

    float4 w4[16];
    const float4* wp = (const float4*)(W + tid * 64);
#pragma unroll
    for (int i = 0; i < 16; ++i) w4[i] = wp[i];

    if (blockIdx.x < 512) {
        const int r0 = blockIdx.x * AR;
        for (int i = tid; i < AR * 64; i += 256) {
            int r = i >> 6, d = i & 63;
            sh[d * 20 + r] = E[(r0 + r) * 64 + d];
        }
        __syncthreads();

        float acc[AR];
#pragma unroll
        for (int r = 0; r < AR; ++r) acc[r] = 0.f;

#pragma unroll
        for (int d4 = 0; d4 < 16; ++d4) {
            float wv4[4] = {w4[d4].x, w4[d4].y, w4[d4].z, w4[d4].w};
#pragma unroll
            for (int s = 0; s < 4; ++s) {
                int d = d4 * 4 + s;
                float wv = wv4[s];
                const float4* ep = (const float4*)(sh + d * 20);
                float4 e0 = ep[0], e1 = ep[1], e2 = ep[2], e3 = ep[3];
                acc[0]  = fmaf(e0.x, wv, acc[0]);
                acc[1]  = fmaf(e0.y, wv, acc[1]);
                acc[2]  = fmaf(e0.z, wv, acc[2]);
                acc[3]  = fmaf(e0.w, wv, acc[3]);
                acc[4]  = fmaf(e1.x, wv, acc[4]);
                acc[5]  = fmaf(e1.y, wv, acc[5]);
                acc[6]  = fmaf(e1.z, wv, acc[6]);
                acc[7]  = fmaf(e1.w, wv, acc[7]);
                acc[8]  = fmaf(e2.x, wv, acc[8]);
                acc[9]  = fmaf(e2.y, wv, acc[9]);
                acc[10] = fmaf(e2.z, wv, acc[10]);
                acc[11] = fmaf(e2.w, wv, acc[11]);
                acc[12] = fmaf(e3.x, wv, acc[12]);
                acc[13] = fmaf(e3.y, wv, acc[13]);
                acc[14] = fmaf(e3.z, wv, acc[14]);
                acc[15] = fmaf(e3.w, wv, acc[15]);
            }
        }
#pragma unroll
        for (int r = 0; r < AR; ++r) g_A[(r0 + r) * 256 + tid] = acc[r];
    } else {
        const int p = blockIdx.x - 512;
        if (tid < 32) {
            float div = expf(-(float)tid * 0.28782313662425572f); // ln(1e4)/32
            float ang = (float)p * div;
            sh[2 * tid]     = sinf(ang);
            sh[2 * tid + 1] = cosf(ang);
        }
        __syncthreads();

        float a0 = 0.f, a1 = 0.f, a2 = 0.f, a3 = 0.f;
#pragma unroll
        for (int i = 0; i < 16; ++i) {
            a0 = fmaf(sh[4 * i + 0], w4[i].x, a0);
            a1 = fmaf(sh[4 * i + 1], w4[i].y, a1);
            a2 = fmaf(sh[4 * i + 2], w4[i].z, a2);
            a3 = fmaf(sh[4 * i + 3], w4[i].w, a3);
        }
        g_P[p * 256 + tid] = (a0 + a1) + (a2 + a3);
    }
}

// ---------------------------------------------------------------------------
// Kernel 2: persistent TMA-bulk-store kernel. 512 threads, 1 CTA/SM,
// double-buffered 2 x 64KB SMEM tile buffers.
// Per tile: compute 64KB into SMEM (8 float4/thread), then tid0 issues
// 8 x 8KB cp.async.bulk (shared -> global, contiguous runs per m1).
// The TMA engine manages in-flight depth — bypasses the per-SM STG queue
// that capped the LSU path at ~5 TB/s.
// ---------------------------------------------------------------------------
__global__ void __launch_bounds__(512, 1) etoc_tma_kernel(
    const float* __restrict__ m1g,
    const float* __restrict__ m2g,
    float* __restrict__ out)
{
    extern __shared__ float sbuf[];      // 2 * 16384 floats (128 KB)
    const int tid = threadIdx.x;
    const int cq  = tid & 63;            // float4 column index (c/4)
    const int grp = tid >> 6;            // m2 index 0..7

    float4 Pr[8];
#pragma unroll
    for (int m1 = 0; m1 < 8; ++m1)
        Pr[m1] = *(const float4*)(g_P + (m1 * 8 + grp) * 256 + 4 * cq);

    int t = blockIdx.x;

    // Prologue loads for first tile
    int b  = t >> 10, i1 = (t >> 5) & 31, j1 = t & 31;
    float4 a4  = *(const float4*)(g_A + t * 256 + 4 * cq);
    float  m1v = __ldg(m1g + b * 32 + i1);
    float  m2v = __ldg(m2g + b * 32 + ((j1 * 8 + grp) & 31));

    int it = 0;
    while (true) {
        float* buf = sbuf + (it & 1) * 16384;

        // Recycle buffer: group issued 2 iterations ago must have drained.
        if (tid == 0 && it >= 2)
            asm volatile("cp.async.bulk.wait_group 1;" ::: "memory");
        __syncthreads();

        // Prefetch next tile's A row + masks (in flight during STS phase)
        int tn = t + GRID;
        bool more = tn < NT;
        float4 a4n;
        float  m1n = 0.f, m2n = 0.f;
        if (more) {
            int bn = tn >> 10, i1n = (tn >> 5) & 31, j1n = tn & 31;
            a4n = *(const float4*)(g_A + tn * 256 + 4 * cq);
            m1n = __ldg(m1g + bn * 32 + i1n);
            m2n = __ldg(m2g + bn * 32 + ((j1n * 8 + grp) & 31));
        }

        // Compute + STS current tile into buffer.
        // SMEM layout mirrors GMEM runs: [m1][m2][c] (8 x 8KB contiguous).
        float f = m1v * m2v;
        float4 fa = {f * a4.x, f * a4.y, f * a4.z, f * a4.w};
#pragma unroll
        for (int m1 = 0; m1 < 8; ++m1) {
            float4 p = Pr[m1];
            float4 v;
            v.x = fmaf(f, p.x, fa.x);
            v.y = fmaf(f, p.y, fa.y);
            v.z = fmaf(f, p.z, fa.z);
            v.w = fmaf(f, p.w, fa.w);
            *(float4*)(buf + m1 * 2048 + grp * 256 + 4 * cq) = v;
        }
        __syncthreads();

        if (tid == 0) {
            asm volatile("fence.proxy.async.shared::cta;" ::: "memory");
            uint32_t s0;
            asm("{ .reg .u64 tt; cvta.to.shared.u64 tt, %1; cvt.u32.u64 %0, tt; }"
                : "=r"(s0) : "l"(buf));
            // GMEM base: out[b, i1*8+m1, j1*8 .. j1*8+7, 0..255] per m1
            float* g0 = out +
                ((long)((b * 256 + i1 * 8) * 256 + j1 * 8)) * 256;
#pragma unroll
            for (int m1 = 0; m1 < 8; ++m1) {
                asm volatile(
                    "cp.async.bulk.global.shared::cta.bulk_group [%0], [%1], %2;"
                    :: "l"(g0 + (long)m1 * 65536), "r"(s0 + m1 * 8192),
                       "r"(8192u)
                    : "memory");
            }
            asm volatile("cp.async.bulk.commit_group;" ::: "memory");
        }

        if (!more) break;
        t = tn;
        b = t >> 10; i1 = (t >> 5) & 31; j1 = t & 31;
        a4 = a4n; m1v = m1n; m2v = m2n;
        ++it;
    }

    // Drain all pending bulk stores before SMEM is released.
    if (tid == 0)
        asm volatile("cp.async.bulk.wait_group 0;" ::: "memory");
    __syncthreads();
}

// ---------------------------------------------------------------------------
// Launch
// ---------------------------------------------------------------------------
extern "C" void kernel_launch(void* const* d_in, const int* in_sizes, int n_in,
                              void* d_out, int out_size) {
    const float* E  = (const float*)d_in[0];  // (8,32,32,64)
    const float* m1 = (const float*)d_in[1];  // (8,32,1,1)
    const float* m2 = (const float*)d_in[2];  // (8,1,32,1)
    const float* W  = (const float*)d_in[3];  // (256,64)

    prep_kernel<<<512 + 64, 256>>>(E, W);

    size_t smem_bytes = 2 * 16384 * sizeof(float);   // 128 KB
    cudaFuncSetAttribute(etoc_tma_kernel,
                         cudaFuncAttributeMaxDynamicSharedMemorySize,
                         (int)smem_bytes);
    etoc_tma_kernel<<<GRID, 512, smem_bytes>>>(m1, m2, (float*)d_out);
}

// round 10
// speedup vs baseline: 1.1983x; 1.1803x over previous
#include <cuda_runtime.h>
#include <math.h>
#include <stdint.h>

#define NT   8192        // tiles: bs(8) * n(32) * n(32)
#define NSM  148         // sm_100a
#define GRID NSM         // 1 CTA/SM persistent

static __device__ float g_P[64 * 256];     // P[pair][c], pair = m1*8+m2

// ---------------------------------------------------------------------------
// Kernel 1: P[p][c] = sum_d pe[p][d] * W[c][d]   (64 blocks, ~2-3 us)
// W row register-resident (16 independent LDG.128), 4 accumulator chains.
// ---------------------------------------------------------------------------
__global__ void __launch_bounds__(256) compute_P_kernel(const float* __restrict__ W)
{
    __shared__ float pe[64];
    const int tid = threadIdx.x;
    const int p   = blockIdx.x;

    float4 w4[16];
    const float4* wp = (const float4*)(W + tid * 64);
#pragma unroll
    for (int i = 0; i < 16; ++i) w4[i] = wp[i];

    if (tid < 32) {
        float div = expf(-(float)tid * 0.28782313662425572f); // ln(1e4)/32
        float ang = (float)p * div;
        pe[2 * tid]     = sinf(ang);
        pe[2 * tid + 1] = cosf(ang);
    }
    __syncthreads();

    float a0 = 0.f, a1 = 0.f, a2 = 0.f, a3 = 0.f;
#pragma unroll
    for (int i = 0; i < 16; ++i) {
        a0 = fmaf(pe[4 * i + 0], w4[i].x, a0);
        a1 = fmaf(pe[4 * i + 1], w4[i].y, a1);
        a2 = fmaf(pe[4 * i + 2], w4[i].z, a2);
        a3 = fmaf(pe[4 * i + 3], w4[i].w, a3);
    }
    g_P[p * 256 + tid] = (a0 + a1) + (a2 + a3);
}

// ---------------------------------------------------------------------------
// Kernel 2: fused persistent GEMV + TMA-bulk-store kernel.
// 512 threads, 1 CTA/SM, double-buffered 2 x 64KB SMEM output buffers.
//
// Per tile (b,i1,j1):
//   phase A: tid<256  : a[c] = E_row . W[c]  (Wt pad-257 SMEM, conflict-free;
//                       E row broadcast from SMEM as float4)
//            tid 256..271: prefetch next tile's E row into the other easm buf
//            all       : prefetch next masks
//   sync
//   phase B: all: 8x float4 = mask*(a+P) -> STS into buffer
//   sync
//   tid0: fence.proxy.async + 8 x 8KB cp.async.bulk + commit_group
//   (wait_group 1 two tiles later recycles the buffer)
//
// SMEM (floats): Wt[0,16448) pe-padded W^T | easm[16448,16576) 2x64 E rows |
//                av[16576,16832) a[c] | buffers[16832,49600) 2x16384
// ---------------------------------------------------------------------------
__global__ void __launch_bounds__(512, 1) etoc_fused_kernel(
    const float* __restrict__ E,
    const float* __restrict__ m1g,
    const float* __restrict__ m2g,
    const float* __restrict__ Wg,
    float* __restrict__ out)
{
    extern __shared__ float sm[];
    float* Wt   = sm;                 // 64 * 257
    float* ea   = sm + 16448;         // 2 * 64
    float* av   = sm + 16576;         // 256
    float* bufs = sm + 16832;         // 2 * 16384

    const int tid = threadIdx.x;
    const int cq  = tid & 63;         // float4 column index (c/4)
    const int grp = tid >> 6;         // m2 index 0..7

    // Stage W transposed, pad-257: coalesced LDG, conflict-free STS/LDS.
    for (int idx = tid; idx < 16384; idx += 512) {
        int c = idx >> 6, d = idx & 63;
        Wt[d * 257 + c] = Wg[idx];
    }

    // P slice in registers
    float4 Pr[8];
#pragma unroll
    for (int m1 = 0; m1 < 8; ++m1)
        Pr[m1] = *(const float4*)(g_P + (m1 * 8 + grp) * 256 + 4 * cq);

    int t = blockIdx.x;

    // Prologue: E row for first tile into easm[0], masks
    int b  = t >> 10, i1 = (t >> 5) & 31, j1 = t & 31;
    if (tid < 16)
        ((float4*)ea)[tid] = ((const float4*)(E + t * 64))[tid];
    float m1v = __ldg(m1g + b * 32 + i1);
    float m2v = __ldg(m2g + b * 32 + ((j1 * 8 + grp) & 31));
    __syncthreads();   // Wt + ea[0] ready

    int it = 0, cur = 0;
    while (true) {
        float* buf = bufs + (it & 1) * 16384;

        // ---- phase A: GEMV + next-tile prefetch ----
        int  tn   = t + GRID;
        bool more = tn < NT;
        float m1n = 0.f, m2n = 0.f;

        if (tid < 256) {
            const float4* e4 = (const float4*)(ea + cur * 64);
            float a0 = 0.f, a1 = 0.f, a2 = 0.f, a3 = 0.f;
#pragma unroll
            for (int i = 0; i < 16; ++i) {
                float4 e = e4[i];
                a0 = fmaf(e.x, Wt[(4 * i + 0) * 257 + tid], a0);
                a1 = fmaf(e.y, Wt[(4 * i + 1) * 257 + tid], a1);
                a2 = fmaf(e.z, Wt[(4 * i + 2) * 257 + tid], a2);
                a3 = fmaf(e.w, Wt[(4 * i + 3) * 257 + tid], a3);
            }
            av[tid] = (a0 + a1) + (a2 + a3);
        } else if (more && tid < 272) {
            ((float4*)(ea + (cur ^ 1) * 64))[tid - 256] =
                ((const float4*)(E + tn * 64))[tid - 256];
        }
        if (more) {
            int bn = tn >> 10, i1n = (tn >> 5) & 31, j1n = tn & 31;
            m1n = __ldg(m1g + bn * 32 + i1n);
            m2n = __ldg(m2g + bn * 32 + ((j1n * 8 + grp) & 31));
        }

        // Buffer recycle: group issued 2 iterations ago must have drained.
        if (tid == 0 && it >= 2)
            asm volatile("cp.async.bulk.wait_group 1;" ::: "memory");
        __syncthreads();   // av ready, ea[nxt] written, buf free

        // ---- phase B: compute + STS 64KB ----
        float  f  = m1v * m2v;
        float4 a4 = *(const float4*)(av + 4 * cq);
        float4 fa = {f * a4.x, f * a4.y, f * a4.z, f * a4.w};
#pragma unroll
        for (int m1 = 0; m1 < 8; ++m1) {
            float4 p = Pr[m1];
            float4 v;
            v.x = fmaf(f, p.x, fa.x);
            v.y = fmaf(f, p.y, fa.y);
            v.z = fmaf(f, p.z, fa.z);
            v.w = fmaf(f, p.w, fa.w);
            *(float4*)(buf + m1 * 2048 + grp * 256 + 4 * cq) = v;
        }
        __syncthreads();

        // ---- TMA issue: 8 x 8KB contiguous runs ----
        if (tid == 0) {
            asm volatile("fence.proxy.async.shared::cta;" ::: "memory");
            uint32_t s0;
            asm("{ .reg .u64 tt; cvta.to.shared.u64 tt, %1; cvt.u32.u64 %0, tt; }"
                : "=r"(s0) : "l"(buf));
            float* g0 = out +
                ((long)((b * 256 + i1 * 8) * 256 + j1 * 8)) * 256;
#pragma unroll
            for (int m1 = 0; m1 < 8; ++m1) {
                asm volatile(
                    "cp.async.bulk.global.shared::cta.bulk_group [%0], [%1], %2;"
                    :: "l"(g0 + (long)m1 * 65536), "r"(s0 + m1 * 8192),
                       "r"(8192u)
                    : "memory");
            }
            asm volatile("cp.async.bulk.commit_group;" ::: "memory");
        }

        if (!more) break;
        t = tn;
        b = t >> 10; i1 = (t >> 5) & 31; j1 = t & 31;
        m1v = m1n; m2v = m2n;
        cur ^= 1; ++it;
    }

    // Drain all pending bulk stores before SMEM is released.
    if (tid == 0)
        asm volatile("cp.async.bulk.wait_group 0;" ::: "memory");
    __syncthreads();
}

// ---------------------------------------------------------------------------
// Launch
// ---------------------------------------------------------------------------
extern "C" void kernel_launch(void* const* d_in, const int* in_sizes, int n_in,
                              void* d_out, int out_size) {
    const float* E  = (const float*)d_in[0];  // (8,32,32,64)
    const float* m1 = (const float*)d_in[1];  // (8,32,1,1)
    const float* m2 = (const float*)d_in[2];  // (8,1,32,1)
    const float* W  = (const float*)d_in[3];  // (256,64)

    compute_P_kernel<<<64, 256>>>(W);

    size_t smem_bytes = 49600 * sizeof(float);   // 198400 B
    cudaFuncSetAttribute(etoc_fused_kernel,
                         cudaFuncAttributeMaxDynamicSharedMemorySize,
                         (int)smem_bytes);
    etoc_fused_kernel<<<GRID, 512, smem_bytes>>>(E, m1, m2, W, (float*)d_out);
}